// round 15
// baseline (speedup 1.0000x reference)
#include <cuda_runtime.h>
#include <math.h>

#define NGEO 1024
#define RROT 1000000
#define EREPN 2000000
#define NGBB (NGEO*4096)
#define ROTLEN (2 + RROT*9)

#define OFF_H     0
#define OFF_DQ    4194304
#define OFF_EREP  4259840
#define OFF_EORB  4260864
#define OFF_RHO   4326400
#define OFF_EELEC 8520704
#define OFF_EREF  8521728

__device__ float g_rot[ROTLEN];
__device__ float g_fockp[NGBB];
__device__ float g_ener2[NGEO];
__device__ float g_V[NGBB];
__device__ int   g_perm[NGEO * 64];
__device__ int   g_ctr;

// ---------------- Kernel 0: reset work-stealing counter ----------------
__global__ void k_zero() { g_ctr = 0; }

// ---------------- Kernel 1: rotation stage ----------------
__global__ void k_rot(const float* __restrict__ net, const float* __restrict__ T,
                      const int* __restrict__ gidx) {
    __shared__ float sT[256 * 27];
    const long base = (long)blockIdx.x * 256;
    const long tb = base * 27;
    const long tmax = (long)RROT * 27;
    for (int i = threadIdx.x; i < 256 * 27; i += 256) {
        long gi = tb + i;
        if (gi < tmax) sT[i] = T[gi];
    }
    __syncthreads();
    long r = base + threadIdx.x;
    float o[9];
    if (r < RROT) {
        int ib = 3 * (int)r;
        float v0 = net[gidx[ib]], v1 = net[gidx[ib + 1]], v2 = net[gidx[ib + 2]];
        const float* t = &sT[threadIdx.x * 27];
#pragma unroll
        for (int j = 0; j < 9; j++)
            o[j] = t[3 * j] * v0 + t[3 * j + 1] * v1 + t[3 * j + 2] * v2;
    }
    __syncthreads();
    float* sO = sT;
    if (r < RROT) {
#pragma unroll
        for (int j = 0; j < 9; j++) sO[threadIdx.x * 9 + j] = o[j];
    }
    __syncthreads();
    long ob = 2 + base * 9;
    for (int i = threadIdx.x; i < 256 * 9; i += 256) {
        long gi = ob + i;
        if (gi < (long)ROTLEN) g_rot[gi] = sO[i];
    }
    if (blockIdx.x == 0 && threadIdx.x == 0) { g_rot[0] = 0.0f; g_rot[1] = 1.0f; }
}

// ---------------- Kernel 2: H gather ----------------
__global__ void k_hgather(const int* __restrict__ oper, float* __restrict__ outH) {
    int i = blockIdx.x * blockDim.x + threadIdx.x;
    int4 idx = ((const int4*)oper)[i];
    float4 v;
    v.x = g_rot[idx.x]; v.y = g_rot[idx.y]; v.z = g_rot[idx.z]; v.w = g_rot[idx.w];
    ((float4*)outH)[i] = v;
}

// ---------------- Kernel 3: dQ, ep, ener2, Fsym, fockp (symmetric) --------
__global__ void k_pre(const float* __restrict__ S, const float* __restrict__ G,
                      const float* __restrict__ rho, const float* __restrict__ qn,
                      const float* __restrict__ phiS, const float* __restrict__ H,
                      float* __restrict__ out_dQ) {
    extern __shared__ float sm[];
    float* b1 = sm;          // S, then T1
    float* b2 = sm + 4160;   // Fsym
    float* b3 = sm + 8320;   // phiS
    __shared__ float sdQ[64], sep[64];
    int g = blockIdx.x, tid = threadIdx.x;
    const float* Sg = S + (size_t)g * 4096;
    const float* Gg = G + (size_t)g * 4096;
    const float* Rg = rho + (size_t)g * 4096;
    const float* Pg = phiS + (size_t)g * 4096;
    const float* Hg = H + (size_t)g * 4096;

    for (int i = tid; i < 4096; i += 256) {
        int r = i >> 6, c = i & 63;
        b1[r * 65 + c] = Sg[i];
        b3[r * 65 + c] = Pg[i];
    }
    __syncthreads();
    int w = tid >> 5, lane = tid & 31;
    for (int rr = 0; rr < 8; rr++) {
        int row = w * 8 + rr;
        float x = Rg[row * 64 + lane] * b1[row * 65 + lane]
                + Rg[row * 64 + lane + 32] * b1[row * 65 + lane + 32];
        for (int o = 16; o; o >>= 1) x += __shfl_xor_sync(0xffffffffu, x, o);
        if (!lane) sdQ[row] = qn[g * 64 + row] - x;
    }
    __syncthreads();
    for (int rr = 0; rr < 8; rr++) {
        int row = w * 8 + rr;
        float x = Gg[row * 64 + lane] * sdQ[lane]
                + Gg[row * 64 + lane + 32] * sdQ[lane + 32];
        for (int o = 16; o; o >>= 1) x += __shfl_xor_sync(0xffffffffu, x, o);
        if (!lane) sep[row] = x;
    }
    __syncthreads();
    if (tid < 64) out_dQ[g * 64 + tid] = sdQ[tid];
    if (tid < 32) {
        float e = sdQ[tid] * sep[tid] + sdQ[tid + 32] * sep[tid + 32];
        for (int o = 16; o; o >>= 1) e += __shfl_xor_sync(0xffffffffu, e, o);
        if (!tid) g_ener2[g] = 0.5f * e;
    }
    for (int i = tid; i < 4096; i += 256) {
        int r = i >> 6, c = i & 63;
        b2[r * 65 + c] = 0.5f * (Hg[i] + Hg[c * 64 + r])
                       - 0.5f * b1[r * 65 + c] * (sep[r] + sep[c]);
    }
    __syncthreads();
    int tx = tid & 15, ty = tid >> 4, r0 = ty * 4, c0 = tx * 4;
    float acc[4][4];
#pragma unroll
    for (int i = 0; i < 4; i++)
#pragma unroll
        for (int j = 0; j < 4; j++) acc[i][j] = 0.0f;
    for (int k = 0; k < 64; k++) {
        float a0 = b2[(r0 + 0) * 65 + k], a1 = b2[(r0 + 1) * 65 + k];
        float a2 = b2[(r0 + 2) * 65 + k], a3 = b2[(r0 + 3) * 65 + k];
        float q0 = b3[k * 65 + c0], q1 = b3[k * 65 + c0 + 1];
        float q2 = b3[k * 65 + c0 + 2], q3 = b3[k * 65 + c0 + 3];
        acc[0][0] += a0 * q0; acc[0][1] += a0 * q1; acc[0][2] += a0 * q2; acc[0][3] += a0 * q3;
        acc[1][0] += a1 * q0; acc[1][1] += a1 * q1; acc[1][2] += a1 * q2; acc[1][3] += a1 * q3;
        acc[2][0] += a2 * q0; acc[2][1] += a2 * q1; acc[2][2] += a2 * q2; acc[2][3] += a2 * q3;
        acc[3][0] += a3 * q0; acc[3][1] += a3 * q1; acc[3][2] += a3 * q2; acc[3][3] += a3 * q3;
    }
    __syncthreads();
#pragma unroll
    for (int i = 0; i < 4; i++)
#pragma unroll
        for (int j = 0; j < 4; j++) b1[(r0 + i) * 65 + c0 + j] = acc[i][j];
    __syncthreads();
#pragma unroll
    for (int i = 0; i < 4; i++)
#pragma unroll
        for (int j = 0; j < 4; j++) acc[i][j] = 0.0f;
    for (int k = 0; k < 64; k++) {
        float a0 = b3[k * 65 + r0 + 0], a1 = b3[k * 65 + r0 + 1];
        float a2 = b3[k * 65 + r0 + 2], a3 = b3[k * 65 + r0 + 3];
        float q0 = b1[k * 65 + c0], q1 = b1[k * 65 + c0 + 1];
        float q2 = b1[k * 65 + c0 + 2], q3 = b1[k * 65 + c0 + 3];
        acc[0][0] += a0 * q0; acc[0][1] += a0 * q1; acc[0][2] += a0 * q2; acc[0][3] += a0 * q3;
        acc[1][0] += a1 * q0; acc[1][1] += a1 * q1; acc[1][2] += a1 * q2; acc[1][3] += a1 * q3;
        acc[2][0] += a2 * q0; acc[2][1] += a2 * q1; acc[2][2] += a2 * q2; acc[2][3] += a2 * q3;
        acc[3][0] += a3 * q0; acc[3][1] += a3 * q1; acc[3][2] += a3 * q2; acc[3][3] += a3 * q3;
    }
    float* fo = g_fockp + (size_t)g * 4096;
#pragma unroll
    for (int i = 0; i < 4; i++)
#pragma unroll
        for (int j = 0; j < 4; j++) fo[(r0 + i) * 64 + c0 + j] = acc[i][j];
}

// ---------------- Kernel 4: Erep ----------------
__global__ void k_erep(const float* __restrict__ net, const int* __restrict__ gr,
                       const int* __restrict__ seg, float* __restrict__ out_erep) {
    __shared__ int sbnd[2];
    __shared__ float sred[256];
    int g = blockIdx.x, tid = threadIdx.x;
    if (tid < 2) {
        int target = g + tid, lo = 0, hi = EREPN;
        while (lo < hi) {
            int mid = (lo + hi) >> 1;
            if (seg[mid] < target) lo = mid + 1; else hi = mid;
        }
        sbnd[tid] = lo;
    }
    __syncthreads();
    float s = 0.0f;
    for (int i = sbnd[0] + tid; i < sbnd[1]; i += 256) s += net[gr[i]];
    sred[tid] = s;
    __syncthreads();
    for (int o = 128; o; o >>= 1) {
        if (tid < o) sred[tid] += sred[tid + o];
        __syncthreads();
    }
    if (!tid) out_erep[g] = sred[0];
}

// ---------------- Kernel 5: persistent work-stealing Brent-Luk Jacobi ------
// Body is bit-identical to R13's per-geometry math (branchless approx coeffs,
// threshold 1e-8, sweep-granularity checks). Only the geometry->CTA mapping
// changes (atomic work stealing), which cannot affect per-geometry results.
__global__ void __launch_bounds__(256, 4) k_jac(float* __restrict__ out) {
    extern __shared__ float sm[];           // 4160 floats: staging / exchange
    __shared__ float4 scs4[16];             // (c,s) pairs, 16B-aligned
    __shared__ float sd[64], sred[256], sfrob;
    __shared__ int sflag, sg;
    float2* scs = (float2*)scs4;
    int tid = threadIdx.x;
    int w = tid >> 5, l = tid & 31;

    for (;;) {
        if (!tid) sg = atomicAdd(&g_ctr, 1);
        __syncthreads();                    // publishes sg; fences sm reuse
        int g = sg;
        if (g >= NGEO) return;
        const float* fp = g_fockp + (size_t)g * 4096;

        // stage fockp (already symmetric)
        for (int i = tid; i < 4096; i += 256) {
            int r = i >> 6, c = i & 63;
            sm[r * 65 + c] = fp[i];
        }
        __syncthreads();

        float A0[8], A1[8], V0[8], V1[8];
        float fl = 0.0f;
#pragma unroll
        for (int j = 0; j < 8; j++) {
            int cg = 8 * w + j;
            A0[j] = sm[(2 * l) * 65 + cg];
            A1[j] = sm[(2 * l + 1) * 65 + cg];
            fl += A0[j] * A0[j] + A1[j] * A1[j];
            V0[j] = (2 * l == cg) ? 1.0f : 0.0f;
            V1[j] = (2 * l + 1 == cg) ? 1.0f : 0.0f;
        }
        sred[tid] = fl;
        __syncthreads();
        for (int o = 128; o; o >>= 1) {
            if (tid < o) sred[tid] += sred[tid + o];
            __syncthreads();
        }
        if (!tid) { sfrob = sred[0]; sflag = 0; }
        __syncthreads();

        float2* xb = (float2*)sm;

        for (int sweep = 0; sweep < 16; sweep++) {
            for (int rnd = 0; rnd < 63; rnd++) {
                // branchless coefficients, approx MUFU math
                {
                    int j = l & 3;
                    float app = A0[2 * j], aqq = A1[2 * j + 1], apq = A0[2 * j + 1];
                    float tau = __fdividef(aqq - app, 2.0f * apq);
                    float sq;
                    asm("sqrt.approx.f32 %0, %1;" : "=f"(sq) : "f"(fmaf(tau, tau, 1.0f)));
                    float rr;
                    asm("rcp.approx.f32 %0, %1;" : "=f"(rr) : "f"(fabsf(tau) + sq));
                    float t = copysignf(rr, tau);
                    float c;
                    asm("rsqrt.approx.f32 %0, %1;" : "=f"(c) : "f"(fmaf(t, t, 1.0f)));
                    float s = t * c;
                    if (fabsf(apq) < 1e-30f) { c = 1.0f; s = 0.0f; }
                    if ((l >> 2) == w) scs[l] = make_float2(c, s);
                }
                __syncthreads();
                float4 qa = scs4[2 * w], qb = scs4[2 * w + 1];
                float2 crs = scs[l];
                float cr = crs.x, sr = crs.y;
                float ccs[4] = {qa.x, qa.z, qb.x, qb.z};
                float sss[4] = {qa.y, qa.w, qb.y, qb.w};
                // right rotation on column pairs
#pragma unroll
                for (int jj = 0; jj < 4; jj++) {
                    float cc = ccs[jj], s2 = sss[jj];
                    int a = 2 * jj, b = a + 1;
                    float x, y;
                    x = A0[a]; y = A0[b]; A0[a] = cc * x - s2 * y; A0[b] = s2 * x + cc * y;
                    x = A1[a]; y = A1[b]; A1[a] = cc * x - s2 * y; A1[b] = s2 * x + cc * y;
                    x = V0[a]; y = V0[b]; V0[a] = cc * x - s2 * y; V0[b] = s2 * x + cc * y;
                    x = V1[a]; y = V1[b]; V1[a] = cc * x - s2 * y; V1[b] = s2 * x + cc * y;
                }
                // left rotation + row migration
#pragma unroll
                for (int j = 0; j < 8; j++) {
                    float x = A0[j], y = A1[j];
                    float r0 = cr * x - sr * y;
                    float r1 = sr * x + cr * y;
                    float tmp = (l == 0) ? r1 : r0;
                    float up = __shfl_up_sync(0xffffffffu, tmp, 1);
                    float dn = __shfl_down_sync(0xffffffffu, r1, 1);
                    A0[j] = (l == 0) ? r0 : up;
                    A1[j] = (l == 31) ? r0 : dn;
                }
                // stage boundary columns
                xb[(w * 4 + 0) * 32 + l] = make_float2(A0[6], A1[6]);
                xb[(w * 4 + 1) * 32 + l] = make_float2(A0[1], A1[1]);
                xb[(w * 4 + 2) * 32 + l] = make_float2(V0[6], V1[6]);
                xb[(w * 4 + 3) * 32 + l] = make_float2(V0[1], V1[1]);
                __syncthreads();
                // column migration
                {
                    float a1_0 = A0[1], a1_1 = A1[1], a6_0 = A0[6], a6_1 = A1[6];
                    float v1_0 = V0[1], v1_1 = V1[1], v6_0 = V0[6], v6_1 = V1[6];
                    A0[6] = A0[4]; A1[6] = A1[4]; A0[4] = A0[2]; A1[4] = A1[2];
                    V0[6] = V0[4]; V1[6] = V1[4]; V0[4] = V0[2]; V1[4] = V1[2];
                    if (w == 0) { A0[2] = a1_0; A1[2] = a1_1; V0[2] = v1_0; V1[2] = v1_1; }
                    else        { A0[2] = A0[0]; A1[2] = A1[0]; V0[2] = V0[0]; V1[2] = V1[0]; }
                    if (w > 0) {
                        float2 ra = xb[((w - 1) * 4 + 0) * 32 + l];
                        float2 rv = xb[((w - 1) * 4 + 2) * 32 + l];
                        A0[0] = ra.x; A1[0] = ra.y; V0[0] = rv.x; V1[0] = rv.y;
                    }
                    A0[1] = A0[3]; A1[1] = A1[3]; A0[3] = A0[5]; A1[3] = A1[5];
                    A0[5] = A0[7]; A1[5] = A1[7];
                    V0[1] = V0[3]; V1[1] = V1[3]; V0[3] = V0[5]; V1[3] = V1[5];
                    V0[5] = V0[7]; V1[5] = V1[7];
                    if (w == 7) { A0[7] = a6_0; A1[7] = a6_1; V0[7] = v6_0; V1[7] = v6_1; }
                    else {
                        float2 ra = xb[((w + 1) * 4 + 1) * 32 + l];
                        float2 rv = xb[((w + 1) * 4 + 3) * 32 + l];
                        A0[7] = ra.x; A1[7] = ra.y; V0[7] = rv.x; V1[7] = rv.y;
                    }
                }
            }
            if (sweep < 3) continue;
            // sweep-end convergence check (identity order)
            float off = 0.0f;
#pragma unroll
            for (int j = 0; j < 8; j++) {
                int cg = 8 * w + j;
                if (2 * l != cg)     off += A0[j] * A0[j];
                if (2 * l + 1 != cg) off += A1[j] * A1[j];
            }
            sred[tid] = off;
            __syncthreads();
            for (int o = 128; o; o >>= 1) {
                if (tid < o) sred[tid] += sred[tid + o];
                __syncthreads();
            }
            if (!tid && sred[0] <= 1e-8f * sfrob) sflag = 1;
            __syncthreads();
            if (sflag) break;
        }

        // dump V to shared staging, extract eigenvalues
        __syncthreads();
#pragma unroll
        for (int j = 0; j < 8; j++) {
            int cg = 8 * w + j;
            sm[(2 * l) * 65 + cg] = V0[j];
            sm[(2 * l + 1) * 65 + cg] = V1[j];
            if (2 * l == cg)     sd[cg] = A0[j];
            if (2 * l + 1 == cg) sd[cg] = A1[j];
        }
        __syncthreads();
        float* Vg = g_V + (size_t)g * 4096;
        for (int i = tid; i < 4096; i += 256) {
            int r = i >> 6, c = i & 63;
            Vg[i] = sm[r * 65 + c];
        }
        if (tid < 64) {
            float d = sd[tid];
            int r = 0;
            for (int jj = 0; jj < 64; jj++)
                r += (sd[jj] < d) || (sd[jj] == d && jj < tid);
            g_perm[g * 64 + r] = tid;
            out[OFF_EORB + g * 64 + r] = d;
        }
    }
}

// ---------------- Kernel 5b: post-eig GEMMs + rho_out + energies -----------
__global__ void k_post(const float* __restrict__ phiS, const float* __restrict__ occ,
                       const float* __restrict__ outH, float* __restrict__ out) {
    extern __shared__ float sm[];
    float* b1 = sm;          // orb_filled
    float* b2 = sm + 4160;   // V
    float* b3 = sm + 8320;   // phiS
    __shared__ float sred[256];
    __shared__ int scol[64];
    int g = blockIdx.x, tid = threadIdx.x;
    const float* Vg = g_V + (size_t)g * 4096;
    const float* Pg = phiS + (size_t)g * 4096;
    for (int i = tid; i < 4096; i += 256) {
        int r = i >> 6, c = i & 63;
        b2[r * 65 + c] = Vg[i];
        b3[r * 65 + c] = Pg[i];
    }
    if (tid < 64) scol[tid] = g_perm[g * 64 + tid];
    __syncthreads();

    int tx = tid & 15, ty = tid >> 4, r0 = ty * 4, c0 = tx * 4;
    const float* Og = occ + (size_t)g * 4096;
    const float* Hg = outH + (size_t)g * 4096;
    float acc[4][4];
    int j0 = scol[c0], j1 = scol[c0 + 1], j2 = scol[c0 + 2], j3 = scol[c0 + 3];
#pragma unroll
    for (int i = 0; i < 4; i++)
#pragma unroll
        for (int j = 0; j < 4; j++) acc[i][j] = 0.0f;
    for (int k = 0; k < 64; k++) {
        float a0 = b3[(r0 + 0) * 65 + k], a1 = b3[(r0 + 1) * 65 + k];
        float a2 = b3[(r0 + 2) * 65 + k], a3 = b3[(r0 + 3) * 65 + k];
        float q0 = b2[k * 65 + j0], q1 = b2[k * 65 + j1];
        float q2 = b2[k * 65 + j2], q3 = b2[k * 65 + j3];
        acc[0][0] += a0 * q0; acc[0][1] += a0 * q1; acc[0][2] += a0 * q2; acc[0][3] += a0 * q3;
        acc[1][0] += a1 * q0; acc[1][1] += a1 * q1; acc[1][2] += a1 * q2; acc[1][3] += a1 * q3;
        acc[2][0] += a2 * q0; acc[2][1] += a2 * q1; acc[2][2] += a2 * q2; acc[2][3] += a2 * q3;
        acc[3][0] += a3 * q0; acc[3][1] += a3 * q1; acc[3][2] += a3 * q2; acc[3][3] += a3 * q3;
    }
#pragma unroll
    for (int i = 0; i < 4; i++)
#pragma unroll
        for (int j = 0; j < 4; j++)
            b1[(r0 + i) * 65 + c0 + j] = Og[(r0 + i) * 64 + c0 + j] * acc[i][j];
    __syncthreads();
#pragma unroll
    for (int i = 0; i < 4; i++)
#pragma unroll
        for (int j = 0; j < 4; j++) acc[i][j] = 0.0f;
    for (int k = 0; k < 64; k++) {
        float a0 = b1[(r0 + 0) * 65 + k], a1 = b1[(r0 + 1) * 65 + k];
        float a2 = b1[(r0 + 2) * 65 + k], a3 = b1[(r0 + 3) * 65 + k];
        float q0 = b1[(c0 + 0) * 65 + k], q1 = b1[(c0 + 1) * 65 + k];
        float q2 = b1[(c0 + 2) * 65 + k], q3 = b1[(c0 + 3) * 65 + k];
        acc[0][0] += a0 * q0; acc[0][1] += a0 * q1; acc[0][2] += a0 * q2; acc[0][3] += a0 * q3;
        acc[1][0] += a1 * q0; acc[1][1] += a1 * q1; acc[1][2] += a1 * q2; acc[1][3] += a1 * q3;
        acc[2][0] += a2 * q0; acc[2][1] += a2 * q1; acc[2][2] += a2 * q2; acc[2][3] += a2 * q3;
        acc[3][0] += a3 * q0; acc[3][1] += a3 * q1; acc[3][2] += a3 * q2; acc[3][3] += a3 * q3;
    }
    float* Ro = out + OFF_RHO + (size_t)g * 4096;
    float e1 = 0.0f;
#pragma unroll
    for (int i = 0; i < 4; i++)
#pragma unroll
        for (int j = 0; j < 4; j++) {
            float v = 2.0f * acc[i][j];
            Ro[(r0 + i) * 64 + c0 + j] = v;
            e1 += v * Hg[(r0 + i) * 64 + c0 + j];
        }
    sred[tid] = e1;
    __syncthreads();
    for (int o = 128; o; o >>= 1) {
        if (tid < o) sred[tid] += sred[tid + o];
        __syncthreads();
    }
    if (!tid) out[OFF_EELEC + g] = sred[0] + g_ener2[g];
}

// ---------------- Kernel 6: Eref ----------------
__global__ void k_eref(const float* __restrict__ zc, const float* __restrict__ rv,
                       float* __restrict__ out) {
    if (threadIdx.x == 0) {
        float s = 0.0f;
        for (int i = 0; i < 7; i++) s += zc[i] * rv[i];
        out[OFF_EREF] = s;
    }
}

extern "C" void kernel_launch(void* const* d_in, const int* in_sizes, int n_in,
                              void* d_out, int out_size) {
    const float* net   = (const float*)d_in[0];
    const float* rotT  = (const float*)d_in[1];
    const float* S     = (const float*)d_in[2];
    const float* G     = (const float*)d_in[3];
    const float* rho   = (const float*)d_in[4];
    const float* qn    = (const float*)d_in[5];
    const float* occ   = (const float*)d_in[6];
    const float* phiS  = (const float*)d_in[7];
    const float* zc    = (const float*)d_in[8];
    const float* rv    = (const float*)d_in[9];
    const int* grot    = (const int*)d_in[10];
    const int* goper   = (const int*)d_in[11];
    const int* grep    = (const int*)d_in[12];
    const int* segrep  = (const int*)d_in[13];
    float* out = (float*)d_out;

    static bool attr_done = false;
    if (!attr_done) {
        cudaFuncSetAttribute(k_pre, cudaFuncAttributeMaxDynamicSharedMemorySize, 49920);
        cudaFuncSetAttribute(k_post, cudaFuncAttributeMaxDynamicSharedMemorySize, 49920);
        attr_done = true;
    }

    k_zero<<<1, 1>>>();
    k_rot<<<(RROT + 255) / 256, 256>>>(net, rotT, grot);
    k_hgather<<<NGBB / 4 / 256, 256>>>(goper, out + OFF_H);
    k_pre<<<NGEO, 256, 49920>>>(S, G, rho, qn, phiS, out + OFF_H, out + OFF_DQ);
    k_jac<<<592, 256, 16640>>>(out);         // persistent, work-stealing
    k_erep<<<NGEO, 256>>>(net, grep, segrep, out + OFF_EREP);
    k_post<<<NGEO, 256, 49920>>>(phiS, occ, out + OFF_H, out);
    k_eref<<<1, 32>>>(zc, rv, out);
}

// round 16
// speedup vs baseline: 1.0925x; 1.0925x over previous
#include <cuda_runtime.h>
#include <math.h>

#define NGEO 1024
#define RROT 1000000
#define EREPN 2000000
#define NGBB (NGEO*4096)
#define ROTLEN (2 + RROT*9)

#define OFF_H     0
#define OFF_DQ    4194304
#define OFF_EREP  4259840
#define OFF_EORB  4260864
#define OFF_RHO   4326400
#define OFF_EELEC 8520704
#define OFF_EREF  8521728

__device__ float g_rot[ROTLEN];
__device__ float g_fockp[NGBB];
__device__ float g_ener2[NGEO];
__device__ float g_V[NGBB];
__device__ int   g_perm[NGEO * 64];

// ---------------- Kernel 1: rotation stage ----------------
__global__ void k_rot(const float* __restrict__ net, const float* __restrict__ T,
                      const int* __restrict__ gidx) {
    __shared__ float sT[256 * 27];
    const long base = (long)blockIdx.x * 256;
    const long tb = base * 27;
    const long tmax = (long)RROT * 27;
    for (int i = threadIdx.x; i < 256 * 27; i += 256) {
        long gi = tb + i;
        if (gi < tmax) sT[i] = T[gi];
    }
    __syncthreads();
    long r = base + threadIdx.x;
    float o[9];
    if (r < RROT) {
        int ib = 3 * (int)r;
        float v0 = net[gidx[ib]], v1 = net[gidx[ib + 1]], v2 = net[gidx[ib + 2]];
        const float* t = &sT[threadIdx.x * 27];
#pragma unroll
        for (int j = 0; j < 9; j++)
            o[j] = t[3 * j] * v0 + t[3 * j + 1] * v1 + t[3 * j + 2] * v2;
    }
    __syncthreads();
    float* sO = sT;
    if (r < RROT) {
#pragma unroll
        for (int j = 0; j < 9; j++) sO[threadIdx.x * 9 + j] = o[j];
    }
    __syncthreads();
    long ob = 2 + base * 9;
    for (int i = threadIdx.x; i < 256 * 9; i += 256) {
        long gi = ob + i;
        if (gi < (long)ROTLEN) g_rot[gi] = sO[i];
    }
    if (blockIdx.x == 0 && threadIdx.x == 0) { g_rot[0] = 0.0f; g_rot[1] = 1.0f; }
}

// ---------------- Kernel 2: H gather ----------------
__global__ void k_hgather(const int* __restrict__ oper, float* __restrict__ outH) {
    int i = blockIdx.x * blockDim.x + threadIdx.x;
    int4 idx = ((const int4*)oper)[i];
    float4 v;
    v.x = g_rot[idx.x]; v.y = g_rot[idx.y]; v.z = g_rot[idx.z]; v.w = g_rot[idx.w];
    ((float4*)outH)[i] = v;
}

// ---------------- Kernel 3: dQ, ep, ener2, Fsym, fockp (symmetric) --------
__global__ void k_pre(const float* __restrict__ S, const float* __restrict__ G,
                      const float* __restrict__ rho, const float* __restrict__ qn,
                      const float* __restrict__ phiS, const float* __restrict__ H,
                      float* __restrict__ out_dQ) {
    extern __shared__ float sm[];
    float* b1 = sm;          // S, then T1
    float* b2 = sm + 4160;   // Fsym
    float* b3 = sm + 8320;   // phiS
    __shared__ float sdQ[64], sep[64];
    int g = blockIdx.x, tid = threadIdx.x;
    const float* Sg = S + (size_t)g * 4096;
    const float* Gg = G + (size_t)g * 4096;
    const float* Rg = rho + (size_t)g * 4096;
    const float* Pg = phiS + (size_t)g * 4096;
    const float* Hg = H + (size_t)g * 4096;

    for (int i = tid; i < 4096; i += 256) {
        int r = i >> 6, c = i & 63;
        b1[r * 65 + c] = Sg[i];
        b3[r * 65 + c] = Pg[i];
    }
    __syncthreads();
    int w = tid >> 5, lane = tid & 31;
    for (int rr = 0; rr < 8; rr++) {
        int row = w * 8 + rr;
        float x = Rg[row * 64 + lane] * b1[row * 65 + lane]
                + Rg[row * 64 + lane + 32] * b1[row * 65 + lane + 32];
        for (int o = 16; o; o >>= 1) x += __shfl_xor_sync(0xffffffffu, x, o);
        if (!lane) sdQ[row] = qn[g * 64 + row] - x;
    }
    __syncthreads();
    for (int rr = 0; rr < 8; rr++) {
        int row = w * 8 + rr;
        float x = Gg[row * 64 + lane] * sdQ[lane]
                + Gg[row * 64 + lane + 32] * sdQ[lane + 32];
        for (int o = 16; o; o >>= 1) x += __shfl_xor_sync(0xffffffffu, x, o);
        if (!lane) sep[row] = x;
    }
    __syncthreads();
    if (tid < 64) out_dQ[g * 64 + tid] = sdQ[tid];
    if (tid < 32) {
        float e = sdQ[tid] * sep[tid] + sdQ[tid + 32] * sep[tid + 32];
        for (int o = 16; o; o >>= 1) e += __shfl_xor_sync(0xffffffffu, e, o);
        if (!tid) g_ener2[g] = 0.5f * e;
    }
    for (int i = tid; i < 4096; i += 256) {
        int r = i >> 6, c = i & 63;
        b2[r * 65 + c] = 0.5f * (Hg[i] + Hg[c * 64 + r])
                       - 0.5f * b1[r * 65 + c] * (sep[r] + sep[c]);
    }
    __syncthreads();
    int tx = tid & 15, ty = tid >> 4, r0 = ty * 4, c0 = tx * 4;
    float acc[4][4];
#pragma unroll
    for (int i = 0; i < 4; i++)
#pragma unroll
        for (int j = 0; j < 4; j++) acc[i][j] = 0.0f;
    for (int k = 0; k < 64; k++) {
        float a0 = b2[(r0 + 0) * 65 + k], a1 = b2[(r0 + 1) * 65 + k];
        float a2 = b2[(r0 + 2) * 65 + k], a3 = b2[(r0 + 3) * 65 + k];
        float q0 = b3[k * 65 + c0], q1 = b3[k * 65 + c0 + 1];
        float q2 = b3[k * 65 + c0 + 2], q3 = b3[k * 65 + c0 + 3];
        acc[0][0] += a0 * q0; acc[0][1] += a0 * q1; acc[0][2] += a0 * q2; acc[0][3] += a0 * q3;
        acc[1][0] += a1 * q0; acc[1][1] += a1 * q1; acc[1][2] += a1 * q2; acc[1][3] += a1 * q3;
        acc[2][0] += a2 * q0; acc[2][1] += a2 * q1; acc[2][2] += a2 * q2; acc[2][3] += a2 * q3;
        acc[3][0] += a3 * q0; acc[3][1] += a3 * q1; acc[3][2] += a3 * q2; acc[3][3] += a3 * q3;
    }
    __syncthreads();
#pragma unroll
    for (int i = 0; i < 4; i++)
#pragma unroll
        for (int j = 0; j < 4; j++) b1[(r0 + i) * 65 + c0 + j] = acc[i][j];
    __syncthreads();
#pragma unroll
    for (int i = 0; i < 4; i++)
#pragma unroll
        for (int j = 0; j < 4; j++) acc[i][j] = 0.0f;
    for (int k = 0; k < 64; k++) {
        float a0 = b3[k * 65 + r0 + 0], a1 = b3[k * 65 + r0 + 1];
        float a2 = b3[k * 65 + r0 + 2], a3 = b3[k * 65 + r0 + 3];
        float q0 = b1[k * 65 + c0], q1 = b1[k * 65 + c0 + 1];
        float q2 = b1[k * 65 + c0 + 2], q3 = b1[k * 65 + c0 + 3];
        acc[0][0] += a0 * q0; acc[0][1] += a0 * q1; acc[0][2] += a0 * q2; acc[0][3] += a0 * q3;
        acc[1][0] += a1 * q0; acc[1][1] += a1 * q1; acc[1][2] += a1 * q2; acc[1][3] += a1 * q3;
        acc[2][0] += a2 * q0; acc[2][1] += a2 * q1; acc[2][2] += a2 * q2; acc[2][3] += a2 * q3;
        acc[3][0] += a3 * q0; acc[3][1] += a3 * q1; acc[3][2] += a3 * q2; acc[3][3] += a3 * q3;
    }
    float* fo = g_fockp + (size_t)g * 4096;
#pragma unroll
    for (int i = 0; i < 4; i++)
#pragma unroll
        for (int j = 0; j < 4; j++) fo[(r0 + i) * 64 + c0 + j] = acc[i][j];
}

// ---------------- Kernel 4: Erep ----------------
__global__ void k_erep(const float* __restrict__ net, const int* __restrict__ gr,
                       const int* __restrict__ seg, float* __restrict__ out_erep) {
    __shared__ int sbnd[2];
    __shared__ float sred[256];
    int g = blockIdx.x, tid = threadIdx.x;
    if (tid < 2) {
        int target = g + tid, lo = 0, hi = EREPN;
        while (lo < hi) {
            int mid = (lo + hi) >> 1;
            if (seg[mid] < target) lo = mid + 1; else hi = mid;
        }
        sbnd[tid] = lo;
    }
    __syncthreads();
    float s = 0.0f;
    for (int i = sbnd[0] + tid; i < sbnd[1]; i += 256) s += net[gr[i]];
    sred[tid] = s;
    __syncthreads();
    for (int o = 128; o; o >>= 1) {
        if (tid < o) sred[tid] += sred[tid + o];
        __syncthreads();
    }
    if (!tid) out_erep[g] = sred[0];
}

// ---------------- Kernel 5: Brent-Luk Jacobi (R13 body, unchanged) --------
__global__ void __launch_bounds__(256, 4) k_jac(float* __restrict__ out) {
    extern __shared__ float sm[];           // 4160 floats: staging / exchange
    __shared__ float4 scs4[16];             // (c,s) pairs, 16B-aligned
    __shared__ float sd[64], sred[256], sfrob;
    __shared__ int sflag;
    float2* scs = (float2*)scs4;
    int g = blockIdx.x, tid = threadIdx.x;
    int w = tid >> 5, l = tid & 31;
    const float* fp = g_fockp + (size_t)g * 4096;

    for (int i = tid; i < 4096; i += 256) {
        int r = i >> 6, c = i & 63;
        sm[r * 65 + c] = fp[i];
    }
    __syncthreads();

    float A0[8], A1[8], V0[8], V1[8];
    float fl = 0.0f;
#pragma unroll
    for (int j = 0; j < 8; j++) {
        int cg = 8 * w + j;
        A0[j] = sm[(2 * l) * 65 + cg];
        A1[j] = sm[(2 * l + 1) * 65 + cg];
        fl += A0[j] * A0[j] + A1[j] * A1[j];
        V0[j] = (2 * l == cg) ? 1.0f : 0.0f;
        V1[j] = (2 * l + 1 == cg) ? 1.0f : 0.0f;
    }
    sred[tid] = fl;
    __syncthreads();
    for (int o = 128; o; o >>= 1) {
        if (tid < o) sred[tid] += sred[tid + o];
        __syncthreads();
    }
    if (!tid) { sfrob = sred[0]; sflag = 0; }
    __syncthreads();

    float2* xb = (float2*)sm;

    for (int sweep = 0; sweep < 16; sweep++) {
        for (int rnd = 0; rnd < 63; rnd++) {
            {
                int j = l & 3;
                float app = A0[2 * j], aqq = A1[2 * j + 1], apq = A0[2 * j + 1];
                float tau = __fdividef(aqq - app, 2.0f * apq);
                float sq;
                asm("sqrt.approx.f32 %0, %1;" : "=f"(sq) : "f"(fmaf(tau, tau, 1.0f)));
                float rr;
                asm("rcp.approx.f32 %0, %1;" : "=f"(rr) : "f"(fabsf(tau) + sq));
                float t = copysignf(rr, tau);
                float c;
                asm("rsqrt.approx.f32 %0, %1;" : "=f"(c) : "f"(fmaf(t, t, 1.0f)));
                float s = t * c;
                if (fabsf(apq) < 1e-30f) { c = 1.0f; s = 0.0f; }
                if ((l >> 2) == w) scs[l] = make_float2(c, s);
            }
            __syncthreads();
            float4 qa = scs4[2 * w], qb = scs4[2 * w + 1];
            float2 crs = scs[l];
            float cr = crs.x, sr = crs.y;
            float ccs[4] = {qa.x, qa.z, qb.x, qb.z};
            float sss[4] = {qa.y, qa.w, qb.y, qb.w};
#pragma unroll
            for (int jj = 0; jj < 4; jj++) {
                float cc = ccs[jj], s2 = sss[jj];
                int a = 2 * jj, b = a + 1;
                float x, y;
                x = A0[a]; y = A0[b]; A0[a] = cc * x - s2 * y; A0[b] = s2 * x + cc * y;
                x = A1[a]; y = A1[b]; A1[a] = cc * x - s2 * y; A1[b] = s2 * x + cc * y;
                x = V0[a]; y = V0[b]; V0[a] = cc * x - s2 * y; V0[b] = s2 * x + cc * y;
                x = V1[a]; y = V1[b]; V1[a] = cc * x - s2 * y; V1[b] = s2 * x + cc * y;
            }
#pragma unroll
            for (int j = 0; j < 8; j++) {
                float x = A0[j], y = A1[j];
                float r0 = cr * x - sr * y;
                float r1 = sr * x + cr * y;
                float tmp = (l == 0) ? r1 : r0;
                float up = __shfl_up_sync(0xffffffffu, tmp, 1);
                float dn = __shfl_down_sync(0xffffffffu, r1, 1);
                A0[j] = (l == 0) ? r0 : up;
                A1[j] = (l == 31) ? r0 : dn;
            }
            xb[(w * 4 + 0) * 32 + l] = make_float2(A0[6], A1[6]);
            xb[(w * 4 + 1) * 32 + l] = make_float2(A0[1], A1[1]);
            xb[(w * 4 + 2) * 32 + l] = make_float2(V0[6], V1[6]);
            xb[(w * 4 + 3) * 32 + l] = make_float2(V0[1], V1[1]);
            __syncthreads();
            {
                float a1_0 = A0[1], a1_1 = A1[1], a6_0 = A0[6], a6_1 = A1[6];
                float v1_0 = V0[1], v1_1 = V1[1], v6_0 = V0[6], v6_1 = V1[6];
                A0[6] = A0[4]; A1[6] = A1[4]; A0[4] = A0[2]; A1[4] = A1[2];
                V0[6] = V0[4]; V1[6] = V1[4]; V0[4] = V0[2]; V1[4] = V1[2];
                if (w == 0) { A0[2] = a1_0; A1[2] = a1_1; V0[2] = v1_0; V1[2] = v1_1; }
                else        { A0[2] = A0[0]; A1[2] = A1[0]; V0[2] = V0[0]; V1[2] = V1[0]; }
                if (w > 0) {
                    float2 ra = xb[((w - 1) * 4 + 0) * 32 + l];
                    float2 rv = xb[((w - 1) * 4 + 2) * 32 + l];
                    A0[0] = ra.x; A1[0] = ra.y; V0[0] = rv.x; V1[0] = rv.y;
                }
                A0[1] = A0[3]; A1[1] = A1[3]; A0[3] = A0[5]; A1[3] = A1[5];
                A0[5] = A0[7]; A1[5] = A1[7];
                V0[1] = V0[3]; V1[1] = V1[3]; V0[3] = V0[5]; V1[3] = V1[5];
                V0[5] = V0[7]; V1[5] = V1[7];
                if (w == 7) { A0[7] = a6_0; A1[7] = a6_1; V0[7] = v6_0; V1[7] = v6_1; }
                else {
                    float2 ra = xb[((w + 1) * 4 + 1) * 32 + l];
                    float2 rv = xb[((w + 1) * 4 + 3) * 32 + l];
                    A0[7] = ra.x; A1[7] = ra.y; V0[7] = rv.x; V1[7] = rv.y;
                }
            }
        }
        if (sweep < 3) continue;
        float off = 0.0f;
#pragma unroll
        for (int j = 0; j < 8; j++) {
            int cg = 8 * w + j;
            if (2 * l != cg)     off += A0[j] * A0[j];
            if (2 * l + 1 != cg) off += A1[j] * A1[j];
        }
        sred[tid] = off;
        __syncthreads();
        for (int o = 128; o; o >>= 1) {
            if (tid < o) sred[tid] += sred[tid + o];
            __syncthreads();
        }
        if (!tid && sred[0] <= 1e-8f * sfrob) sflag = 1;
        __syncthreads();
        if (sflag) break;
    }

    __syncthreads();
#pragma unroll
    for (int j = 0; j < 8; j++) {
        int cg = 8 * w + j;
        sm[(2 * l) * 65 + cg] = V0[j];
        sm[(2 * l + 1) * 65 + cg] = V1[j];
        if (2 * l == cg)     sd[cg] = A0[j];
        if (2 * l + 1 == cg) sd[cg] = A1[j];
    }
    __syncthreads();
    float* Vg = g_V + (size_t)g * 4096;
    for (int i = tid; i < 4096; i += 256) {
        int r = i >> 6, c = i & 63;
        Vg[i] = sm[r * 65 + c];
    }
    if (tid < 64) {
        float d = sd[tid];
        int r = 0;
        for (int jj = 0; jj < 64; jj++)
            r += (sd[jj] < d) || (sd[jj] == d && jj < tid);
        g_perm[g * 64 + r] = tid;
        out[OFF_EORB + g * 64 + r] = d;
    }
}

// ---------------- Kernel 5b: post-eig GEMMs + rho_out + energies -----------
__global__ void k_post(const float* __restrict__ phiS, const float* __restrict__ occ,
                       const float* __restrict__ outH, float* __restrict__ out) {
    extern __shared__ float sm[];
    float* b1 = sm;          // orb_filled
    float* b2 = sm + 4160;   // V
    float* b3 = sm + 8320;   // phiS
    __shared__ float sred[256];
    __shared__ int scol[64];
    int g = blockIdx.x, tid = threadIdx.x;
    const float* Vg = g_V + (size_t)g * 4096;
    const float* Pg = phiS + (size_t)g * 4096;
    for (int i = tid; i < 4096; i += 256) {
        int r = i >> 6, c = i & 63;
        b2[r * 65 + c] = Vg[i];
        b3[r * 65 + c] = Pg[i];
    }
    if (tid < 64) scol[tid] = g_perm[g * 64 + tid];
    __syncthreads();

    int tx = tid & 15, ty = tid >> 4, r0 = ty * 4, c0 = tx * 4;
    const float* Og = occ + (size_t)g * 4096;
    const float* Hg = outH + (size_t)g * 4096;
    float acc[4][4];
    int j0 = scol[c0], j1 = scol[c0 + 1], j2 = scol[c0 + 2], j3 = scol[c0 + 3];
#pragma unroll
    for (int i = 0; i < 4; i++)
#pragma unroll
        for (int j = 0; j < 4; j++) acc[i][j] = 0.0f;
    for (int k = 0; k < 64; k++) {
        float a0 = b3[(r0 + 0) * 65 + k], a1 = b3[(r0 + 1) * 65 + k];
        float a2 = b3[(r0 + 2) * 65 + k], a3 = b3[(r0 + 3) * 65 + k];
        float q0 = b2[k * 65 + j0], q1 = b2[k * 65 + j1];
        float q2 = b2[k * 65 + j2], q3 = b2[k * 65 + j3];
        acc[0][0] += a0 * q0; acc[0][1] += a0 * q1; acc[0][2] += a0 * q2; acc[0][3] += a0 * q3;
        acc[1][0] += a1 * q0; acc[1][1] += a1 * q1; acc[1][2] += a1 * q2; acc[1][3] += a1 * q3;
        acc[2][0] += a2 * q0; acc[2][1] += a2 * q1; acc[2][2] += a2 * q2; acc[2][3] += a2 * q3;
        acc[3][0] += a3 * q0; acc[3][1] += a3 * q1; acc[3][2] += a3 * q2; acc[3][3] += a3 * q3;
    }
#pragma unroll
    for (int i = 0; i < 4; i++)
#pragma unroll
        for (int j = 0; j < 4; j++)
            b1[(r0 + i) * 65 + c0 + j] = Og[(r0 + i) * 64 + c0 + j] * acc[i][j];
    __syncthreads();
#pragma unroll
    for (int i = 0; i < 4; i++)
#pragma unroll
        for (int j = 0; j < 4; j++) acc[i][j] = 0.0f;
    for (int k = 0; k < 64; k++) {
        float a0 = b1[(r0 + 0) * 65 + k], a1 = b1[(r0 + 1) * 65 + k];
        float a2 = b1[(r0 + 2) * 65 + k], a3 = b1[(r0 + 3) * 65 + k];
        float q0 = b1[(c0 + 0) * 65 + k], q1 = b1[(c0 + 1) * 65 + k];
        float q2 = b1[(c0 + 2) * 65 + k], q3 = b1[(c0 + 3) * 65 + k];
        acc[0][0] += a0 * q0; acc[0][1] += a0 * q1; acc[0][2] += a0 * q2; acc[0][3] += a0 * q3;
        acc[1][0] += a1 * q0; acc[1][1] += a1 * q1; acc[1][2] += a1 * q2; acc[1][3] += a1 * q3;
        acc[2][0] += a2 * q0; acc[2][1] += a2 * q1; acc[2][2] += a2 * q2; acc[2][3] += a2 * q3;
        acc[3][0] += a3 * q0; acc[3][1] += a3 * q1; acc[3][2] += a3 * q2; acc[3][3] += a3 * q3;
    }
    float* Ro = out + OFF_RHO + (size_t)g * 4096;
    float e1 = 0.0f;
#pragma unroll
    for (int i = 0; i < 4; i++)
#pragma unroll
        for (int j = 0; j < 4; j++) {
            float v = 2.0f * acc[i][j];
            Ro[(r0 + i) * 64 + c0 + j] = v;
            e1 += v * Hg[(r0 + i) * 64 + c0 + j];
        }
    sred[tid] = e1;
    __syncthreads();
    for (int o = 128; o; o >>= 1) {
        if (tid < o) sred[tid] += sred[tid + o];
        __syncthreads();
    }
    if (!tid) out[OFF_EELEC + g] = sred[0] + g_ener2[g];
}

// ---------------- Kernel 6: Eref ----------------
__global__ void k_eref(const float* __restrict__ zc, const float* __restrict__ rv,
                       float* __restrict__ out) {
    if (threadIdx.x == 0) {
        float s = 0.0f;
        for (int i = 0; i < 7; i++) s += zc[i] * rv[i];
        out[OFF_EREF] = s;
    }
}

extern "C" void kernel_launch(void* const* d_in, const int* in_sizes, int n_in,
                              void* d_out, int out_size) {
    const float* net   = (const float*)d_in[0];
    const float* rotT  = (const float*)d_in[1];
    const float* S     = (const float*)d_in[2];
    const float* G     = (const float*)d_in[3];
    const float* rho   = (const float*)d_in[4];
    const float* qn    = (const float*)d_in[5];
    const float* occ   = (const float*)d_in[6];
    const float* phiS  = (const float*)d_in[7];
    const float* zc    = (const float*)d_in[8];
    const float* rv    = (const float*)d_in[9];
    const int* grot    = (const int*)d_in[10];
    const int* goper   = (const int*)d_in[11];
    const int* grep    = (const int*)d_in[12];
    const int* segrep  = (const int*)d_in[13];
    float* out = (float*)d_out;

    static cudaStream_t s2 = nullptr;
    static cudaEvent_t evFork = nullptr, evJoin = nullptr;
    static bool init_done = false;
    if (!init_done) {
        cudaFuncSetAttribute(k_pre, cudaFuncAttributeMaxDynamicSharedMemorySize, 49920);
        cudaFuncSetAttribute(k_post, cudaFuncAttributeMaxDynamicSharedMemorySize, 49920);
        cudaStreamCreateWithFlags(&s2, cudaStreamNonBlocking);
        cudaEventCreateWithFlags(&evFork, cudaEventDisableTiming);
        cudaEventCreateWithFlags(&evJoin, cudaEventDisableTiming);
        init_done = true;
    }

    // fork: independent leg (Erep, Eref) on stream s2, overlapping the
    // compute-bound main chain (k_jac leaves HBM idle).
    cudaEventRecord(evFork, 0);
    cudaStreamWaitEvent(s2, evFork, 0);
    k_erep<<<NGEO, 256, 0, s2>>>(net, grep, segrep, out + OFF_EREP);
    k_eref<<<1, 32, 0, s2>>>(zc, rv, out);
    cudaEventRecord(evJoin, s2);

    // main chain on the capturing (default) stream
    k_rot<<<(RROT + 255) / 256, 256>>>(net, rotT, grot);
    k_hgather<<<NGBB / 4 / 256, 256>>>(goper, out + OFF_H);
    k_pre<<<NGEO, 256, 49920>>>(S, G, rho, qn, phiS, out + OFF_H, out + OFF_DQ);
    k_jac<<<NGEO, 256, 16640>>>(out);
    k_post<<<NGEO, 256, 49920>>>(phiS, occ, out + OFF_H, out);

    // join
    cudaStreamWaitEvent(0, evJoin, 0);
}